// round 3
// baseline (speedup 1.0000x reference)
#include <cuda_runtime.h>
#include <cuda_bf16.h>
#include <cstdint>

// Problem dims
#define Tdim 2048
#define Bdim 64
#define Kdim 512
#define Odim 512

// Tiling
#define TSTRIP 32
#define NSTRIPS 64           // 2048 / 32
#define MITERS 16            // 32 t / 2 t per M-iter
#define MTILE 128            // 2 t * 64 b
#define OTILE 64             // o columns per CTA (N = 128 combined g|h)
#define KT 32                // K tile
#define KTILES 16            // 512 / 32

// Padded smem strides (floats) — chosen for conflict-free fragment loads
#define XS_STRIDE 36
#define WS_STRIDE 136
#define STG_STRIDE 132

// Shared memory layout (float offsets)
#define XS_OFF   0
#define XS_BUF   (MTILE * XS_STRIDE)            // 4608
#define WS_OFF   (2 * XS_BUF)                   // 9216
#define WS_BUF   (KT * WS_STRIDE)               // 4352
#define STG_OFF  (WS_OFF + 2 * WS_BUF)          // 17920
#define AST_OFF  (STG_OFF + MTILE * STG_STRIDE) // 34816
#define BST_OFF  (AST_OFF + 4096)               // 38912
#define BIAS_OFF (BST_OFF + 4096)               // 43008 (gb,hb,r,rb: 64 each)
#define SMEM_FLOATS (BIAS_OFF + 256)            // 43264
#define SMEM_BYTES  (SMEM_FLOATS * 4)           // 173056

// Per-strip affine transforms: y_out = A*y_in + B, laid out [strip][b*512+o]
__device__ float g_As[NSTRIPS * Bdim * Odim];
__device__ float g_Bs[NSTRIPS * Bdim * Odim];

__device__ __forceinline__ void cp16(float* dst, const float* src) {
    uint32_t d = (uint32_t)__cvta_generic_to_shared(dst);
    asm volatile("cp.async.cg.shared.global [%0], [%1], 16;" :: "r"(d), "l"(src));
}
__device__ __forceinline__ void cp_commit() {
    asm volatile("cp.async.commit_group;" ::: "memory");
}
__device__ __forceinline__ void cp_wait_all() {
    asm volatile("cp.async.wait_group 0;" ::: "memory");
}

__device__ __forceinline__ void load_tiles(
    float* sm, const float* __restrict__ x,
    const float* __restrict__ g, const float* __restrict__ h,
    int m_base, int o_base, int kt, int tid)
{
    const int buf = kt & 1;
    const int k_base = kt * KT;
    // x tile: 128 rows x 32 floats = 1024 x 16B chunks
    float* xs = sm + XS_OFF + buf * XS_BUF;
    #pragma unroll
    for (int j = 0; j < 4; j++) {
        int c   = tid + 256 * j;
        int row = c >> 3;
        int seg = (c & 7) * 4;
        cp16(xs + row * XS_STRIDE + seg,
             x + (size_t)(m_base + row) * Kdim + k_base + seg);
    }
    // w tile: 32 k-rows x 128 cols (cols 0..63 = g, 64..127 = h)
    float* ws = sm + WS_OFF + buf * WS_BUF;
    #pragma unroll
    for (int j = 0; j < 4; j++) {
        int c   = tid + 256 * j;
        int row = c >> 5;         // 0..31
        int n0  = (c & 31) * 4;   // 0..124
        const float* src = (n0 < 64)
            ? g + (size_t)(k_base + row) * Odim + o_base + n0
            : h + (size_t)(k_base + row) * Odim + o_base + (n0 - 64);
        cp16(ws + row * WS_STRIDE + n0, src);
    }
}

__global__ void __launch_bounds__(256, 1)
rnn_gemm_scan(const float* __restrict__ x,  const float* __restrict__ g,
              const float* __restrict__ gb, const float* __restrict__ h,
              const float* __restrict__ hb, const float* __restrict__ r,
              const float* __restrict__ rb)
{
    extern __shared__ float sm[];
    const int tid    = threadIdx.x;
    const int o_base = blockIdx.x * OTILE;
    const int strip  = blockIdx.y;

    // Biases for this o-tile + scan state init
    if (tid < 64) {
        sm[BIAS_OFF + tid]        = gb[o_base + tid];
        sm[BIAS_OFF + 64  + tid]  = hb[o_base + tid];
        sm[BIAS_OFF + 128 + tid]  = r[o_base + tid];
        sm[BIAS_OFF + 192 + tid]  = rb[o_base + tid];
    }
    #pragma unroll
    for (int j = 0; j < 16; j++) {
        sm[AST_OFF + tid + 256 * j] = 1.0f;
        sm[BST_OFF + tid + 256 * j] = 0.0f;
    }

    const int lane = tid & 31;
    const int wid  = tid >> 5;
    const int wm   = (wid & 3) * 32;   // warp row offset (4 warps in M)
    const int wn   = (wid >> 2) * 64;  // warp col offset (2 warps in N)
    const int grp  = lane >> 2;
    const int tig  = lane & 3;
    __syncthreads();

    for (int iter = 0; iter < MITERS; iter++) {
        const int m_base = (strip * TSTRIP + iter * 2) * Bdim;

        float acc[2][8][4];
        #pragma unroll
        for (int mi = 0; mi < 2; mi++)
            #pragma unroll
            for (int ni = 0; ni < 8; ni++)
                #pragma unroll
                for (int e = 0; e < 4; e++) acc[mi][ni][e] = 0.0f;

        load_tiles(sm, x, g, h, m_base, o_base, 0, tid);
        cp_commit();

        for (int kt = 0; kt < KTILES; kt++) {
            cp_wait_all();
            __syncthreads();
            if (kt + 1 < KTILES) {
                load_tiles(sm, x, g, h, m_base, o_base, kt + 1, tid);
                cp_commit();
            }
            const float* xs = sm + XS_OFF + (kt & 1) * XS_BUF;
            const float* ws = sm + WS_OFF + (kt & 1) * WS_BUF;
            #pragma unroll
            for (int kk = 0; kk < KT; kk += 8) {
                uint32_t a[2][4], b[8][2];
                #pragma unroll
                for (int mi = 0; mi < 2; mi++) {
                    int r0 = wm + mi * 16 + grp;
                    a[mi][0] = __float_as_uint(xs[r0 * XS_STRIDE + kk + tig]);
                    a[mi][1] = __float_as_uint(xs[(r0 + 8) * XS_STRIDE + kk + tig]);
                    a[mi][2] = __float_as_uint(xs[r0 * XS_STRIDE + kk + tig + 4]);
                    a[mi][3] = __float_as_uint(xs[(r0 + 8) * XS_STRIDE + kk + tig + 4]);
                }
                #pragma unroll
                for (int ni = 0; ni < 8; ni++) {
                    int col = wn + ni * 8 + grp;
                    b[ni][0] = __float_as_uint(ws[(kk + tig) * WS_STRIDE + col]);
                    b[ni][1] = __float_as_uint(ws[(kk + tig + 4) * WS_STRIDE + col]);
                }
                #pragma unroll
                for (int mi = 0; mi < 2; mi++)
                    #pragma unroll
                    for (int ni = 0; ni < 8; ni++)
                        asm volatile(
                            "mma.sync.aligned.m16n8k8.row.col.f32.tf32.tf32.f32 "
                            "{%0,%1,%2,%3},{%4,%5,%6,%7},{%8,%9},{%0,%1,%2,%3};"
                            : "+f"(acc[mi][ni][0]), "+f"(acc[mi][ni][1]),
                              "+f"(acc[mi][ni][2]), "+f"(acc[mi][ni][3])
                            : "r"(a[mi][0]), "r"(a[mi][1]),
                              "r"(a[mi][2]), "r"(a[mi][3]),
                              "r"(b[ni][0]), "r"(b[ni][1]));
            }
        }

        // Stage accumulators to smem (pre-activation values)
        #pragma unroll
        for (int mi = 0; mi < 2; mi++)
            #pragma unroll
            for (int ni = 0; ni < 8; ni++)
                #pragma unroll
                for (int e = 0; e < 4; e++) {
                    int row = wm + mi * 16 + grp + ((e >= 2) ? 8 : 0);
                    int col = wn + ni * 8 + tig * 2 + (e & 1);
                    sm[STG_OFF + row * STG_STRIDE + col] = acc[mi][ni][e];
                }
        __syncthreads();

        // Gating + scan update (rows 0..63 = t0, 64..127 = t1; cols 0..63 = G, 64..127 = H)
        const float tsc0 = (float)(strip * TSTRIP + iter * 2) * (1.0f / 2048.0f);
        const float tsc1 = tsc0 + (1.0f / 2048.0f);
        #pragma unroll
        for (int j = 0; j < 16; j++) {
            int idx = tid + 256 * j;
            int o   = idx & 63;
            int bb  = idx >> 6;
            float zG0 = sm[STG_OFF + bb * STG_STRIDE + o];
            float zG1 = sm[STG_OFF + (64 + bb) * STG_STRIDE + o];
            float zH0 = sm[STG_OFF + bb * STG_STRIDE + 64 + o];
            float zH1 = sm[STG_OFF + (64 + bb) * STG_STRIDE + 64 + o];
            float gbv = sm[BIAS_OFF + o];
            float hbv = sm[BIAS_OFF + 64 + o];
            float rv  = sm[BIAS_OFF + 128 + o];
            float rbv = sm[BIAS_OFF + 192 + o];
            float rt0 = 2.0f / (1.0f + __expf(-(tsc0 * rv + rbv)));
            float rt1 = 2.0f / (1.0f + __expf(-(tsc1 * rv + rbv)));
            float G0 = rt0 / (1.0f + __expf(-(zG0 + gbv)));
            float G1 = rt1 / (1.0f + __expf(-(zG1 + gbv)));
            float H0 = rt0 * (1.0f - 2.0f / (__expf(2.0f * (zH0 + hbv)) + 1.0f));
            float H1 = rt1 * (1.0f - 2.0f / (__expf(2.0f * (zH1 + hbv)) + 1.0f));
            // chunk transform for these 2 steps: y -> G1*(G0*y + H0) + H1
            float Ac = G1 * G0;
            float Bc = G1 * H0 + H1;
            // compose onto strip state (chunk applied AFTER current state)
            sm[BST_OFF + idx] = Ac * sm[BST_OFF + idx] + Bc;
            sm[AST_OFF + idx] = Ac * sm[AST_OFF + idx];
        }
        // No sync needed: each thread owns the same idx set across iters, and
        // the next iter's first stage overwrite is behind the k-loop syncs.
    }

    // Write strip transform (thread owns same idx set — no sync needed)
    #pragma unroll
    for (int j = 0; j < 16; j++) {
        int idx = tid + 256 * j;
        int o   = idx & 63;
        int bb  = idx >> 6;
        size_t gi = (size_t)(strip * Bdim + bb) * Odim + o_base + o;
        g_As[gi] = sm[AST_OFF + idx];
        g_Bs[gi] = sm[BST_OFF + idx];
    }
}

__global__ void rnn_combine(float* __restrict__ out)
{
    int idx = blockIdx.x * 256 + threadIdx.x;   // = b*512 + o, 32768 total
    float y = 0.0f;
    #pragma unroll 8
    for (int s = 0; s < NSTRIPS; s++) {
        y = g_As[s * (Bdim * Odim) + idx] * y + g_Bs[s * (Bdim * Odim) + idx];
    }
    out[idx] = y;
}

extern "C" void kernel_launch(void* const* d_in, const int* in_sizes, int n_in,
                              void* d_out, int out_size)
{
    const float* x  = (const float*)d_in[0];
    const float* g  = (const float*)d_in[1];
    const float* gb = (const float*)d_in[2];
    const float* h  = (const float*)d_in[3];
    const float* hb = (const float*)d_in[4];
    const float* r  = (const float*)d_in[5];
    const float* rb = (const float*)d_in[6];

    cudaFuncSetAttribute((const void*)rnn_gemm_scan,
                         cudaFuncAttributeMaxDynamicSharedMemorySize, SMEM_BYTES);

    rnn_gemm_scan<<<dim3(8, NSTRIPS), 256, SMEM_BYTES>>>(x, g, gb, h, hb, r, rb);
    rnn_combine<<<(Bdim * Odim) / 256, 256>>>((float*)d_out);
}

// round 7
// speedup vs baseline: 1.2255x; 1.2255x over previous
#include <cuda_runtime.h>
#include <cstdint>

// ---------------- problem dims ----------------
#define Tdim 2048
#define Bdim 64
#define Kdim 512
#define Odim 512

// ---------------- tiling ----------------
#define TSTRIP 32            // timesteps per strip (CTA)
#define NSTRIPS 64           // 2048/32
#define MITERS 16            // 2 timesteps (=128 M rows) per iter
#define KT 32                // K per stage (floats)
#define KTILES 16            // 512/32
#define NTOT (MITERS*KTILES) // 256 stages per CTA
#define STR 36               // smem row stride in floats (32 + 4 pad, conflict-free)
#define STAGE_BYTES (128*STR*4)   // 18432 per operand per stage
#define NSTAGE 4

// smem layout (bytes)
#define SM_A 0
#define SM_B (NSTAGE*STAGE_BYTES)                  // 73728
#define SM_TOTAL (2*NSTAGE*STAGE_BYTES)            // 147456

// ---------------- device scratch ----------------
// combined K-major weights: row n = 2*o + s (s=0:g, s=1:h), cols k
__device__ float g_wT[2 * Odim * Kdim];
__device__ float g_As[NSTRIPS * Bdim * Odim];
__device__ float g_Bs[NSTRIPS * Bdim * Odim];

// ---------------- helpers ----------------
__device__ __forceinline__ uint32_t smem_u32(const void* p) {
    uint32_t a;
    asm("{ .reg .u64 t; cvta.to.shared.u64 t, %1; cvt.u32.u64 %0, t; }" : "=r"(a) : "l"(p));
    return a;
}
__device__ __forceinline__ void cp16(uint32_t dst, const float* src) {
    asm volatile("cp.async.cg.shared.global [%0], [%1], 16;" :: "r"(dst), "l"(src));
}
__device__ __forceinline__ void cp_commit() { asm volatile("cp.async.commit_group;" ::: "memory"); }
__device__ __forceinline__ float tanha(float x) {
    float y; asm("tanh.approx.f32 %0, %1;" : "=f"(y) : "f"(x)); return y;
}

// ---------------- weight prep: g,h -> interleaved K-major g_wT ----------------
__global__ void prep_w(const float* __restrict__ g, const float* __restrict__ h)
{
    __shared__ float t[32][33];
    const int s = blockIdx.z;
    const float* src = s ? h : g;
    const int ob = blockIdx.x * 32, kb = blockIdx.y * 32;
    #pragma unroll
    for (int i = 0; i < 32; i += 8)
        t[threadIdx.y + i][threadIdx.x] = src[(size_t)(kb + threadIdx.y + i) * Odim + ob + threadIdx.x];
    __syncthreads();
    #pragma unroll
    for (int i = 0; i < 32; i += 8)
        g_wT[(size_t)(2 * (ob + threadIdx.y + i) + s) * Kdim + kb + threadIdx.x] = t[threadIdx.x][threadIdx.y + i];
}

// ---------------- stage loader ----------------
__device__ __forceinline__ void load_stage(uint32_t sbase, const float* __restrict__ x,
                                           int strip, int n_base, int ktg, int tid)
{
    const int stage = ktg & 3;
    const int iter = ktg >> 4, kt = ktg & 15;
    const int kbase = kt * KT;
    const int t0 = strip * TSTRIP + iter * 2;
    const uint32_t aB = sbase + SM_A + stage * STAGE_BYTES;
    const uint32_t bB = sbase + SM_B + stage * STAGE_BYTES;
    #pragma unroll
    for (int j = 0; j < 4; j++) {                 // A: 128 rows, row = 2b + tp
        int c = tid + 256 * j;
        int row = c >> 3, seg = c & 7;
        int m = (t0 + (row & 1)) * Bdim + (row >> 1);
        cp16(aB + (row * STR + seg * 4) * 4, x + (size_t)m * Kdim + kbase + seg * 4);
    }
    #pragma unroll
    for (int j = 0; j < 4; j++) {                 // B: 128 rows = interleaved (G,H) cols
        int c = tid + 256 * j;
        int row = c >> 3, seg = c & 7;
        cp16(bB + (row * STR + seg * 4) * 4,
             g_wT + (size_t)(n_base + row) * Kdim + kbase + seg * 4);
    }
}

// ---------------- fragment loader (conflict-free: grp*4+tig banks) ----------------
__device__ __forceinline__ void load_frags(const float* __restrict__ xs,
                                           const float* __restrict__ bs, int kk,
                                           int wm, int wn, int grp, int tig,
                                           uint32_t a[2][4], uint32_t b[8][2])
{
    #pragma unroll
    for (int mi = 0; mi < 2; mi++) {
        int r0 = wm + mi * 16 + grp;
        a[mi][0] = __float_as_uint(xs[r0 * STR + kk + tig]);
        a[mi][1] = __float_as_uint(xs[(r0 + 8) * STR + kk + tig]);
        a[mi][2] = __float_as_uint(xs[r0 * STR + kk + tig + 4]);
        a[mi][3] = __float_as_uint(xs[(r0 + 8) * STR + kk + tig + 4]);
    }
    #pragma unroll
    for (int ni = 0; ni < 8; ni++) {
        int n = wn + ni * 8 + grp;
        b[ni][0] = __float_as_uint(bs[n * STR + kk + tig]);
        b[ni][1] = __float_as_uint(bs[n * STR + kk + tig + 4]);
    }
}

// ---------------- main kernel ----------------
__global__ void __launch_bounds__(256, 1)
rnn_gemm_scan(const float* __restrict__ x,  const float* __restrict__ gb,
              const float* __restrict__ hb, const float* __restrict__ r,
              const float* __restrict__ rb)
{
    extern __shared__ float smf[];
    const uint32_t sbase = smem_u32(smf);
    const int tid = threadIdx.x, lane = tid & 31, wid = tid >> 5;
    const int o_base = blockIdx.x * 64;       // 64 outputs per CTA (N=128 interleaved)
    const int strip  = blockIdx.y;
    const int wm = (wid & 3) * 32;            // 4 warps in M
    const int wn = (wid >> 2) * 64;           // 2 warps in N
    const int grp = lane >> 2, tig = lane & 3;
    const int tp = grp & 1;                   // timestep parity of this thread's rows

    // per-thread output set: ol = wn/2 + ni*4 + tig
    float gbv[8], hbv[8], rv[8], rbv[8];
    #pragma unroll
    for (int ni = 0; ni < 8; ni++) {
        int o = o_base + (wn >> 1) + ni * 4 + tig;
        gbv[ni] = gb[o]; hbv[ni] = hb[o]; rv[ni] = r[o]; rbv[ni] = rb[o];
    }
    // register-resident scan state [mi][hl][ni]
    float sA[2][2][8], sB[2][2][8];
    #pragma unroll
    for (int mi = 0; mi < 2; mi++)
        #pragma unroll
        for (int hl = 0; hl < 2; hl++)
            #pragma unroll
            for (int ni = 0; ni < 8; ni++) { sA[mi][hl][ni] = 1.0f; sB[mi][hl][ni] = 0.0f; }

    const int n_base = o_base * 2;

    // pipeline prologue: 3 stages in flight
    load_stage(sbase, x, strip, n_base, 0, tid); cp_commit();
    load_stage(sbase, x, strip, n_base, 1, tid); cp_commit();
    load_stage(sbase, x, strip, n_base, 2, tid); cp_commit();

    for (int iter = 0; iter < MITERS; iter++) {
        float acc[2][8][4];
        #pragma unroll
        for (int mi = 0; mi < 2; mi++)
            #pragma unroll
            for (int ni = 0; ni < 8; ni++)
                #pragma unroll
                for (int e = 0; e < 4; e++) acc[mi][ni][e] = 0.0f;

        for (int kt = 0; kt < KTILES; kt++) {
            const int ktg = iter * KTILES + kt;
            asm volatile("cp.async.wait_group 2;" ::: "memory");
            __syncthreads();                       // stage ktg ready; stage ktg-1 fully consumed
            if (ktg + 3 < NTOT) load_stage(sbase, x, strip, n_base, ktg + 3, tid);
            cp_commit();                           // always commit (keeps group math exact)

            const float* xs = smf + (SM_A / 4) + (ktg & 3) * (STAGE_BYTES / 4);
            const float* bs = smf + (SM_B / 4) + (ktg & 3) * (STAGE_BYTES / 4);

            uint32_t a[2][2][4], b[2][8][2];
            load_frags(xs, bs, 0, wm, wn, grp, tig, a[0], b[0]);
            #pragma unroll
            for (int kk4 = 0; kk4 < 4; kk4++) {
                const int cur = kk4 & 1;
                if (kk4 < 3)
                    load_frags(xs, bs, (kk4 + 1) * 8, wm, wn, grp, tig, a[cur ^ 1], b[cur ^ 1]);
                #pragma unroll
                for (int mi = 0; mi < 2; mi++)
                    #pragma unroll
                    for (int ni = 0; ni < 8; ni++)
                        asm volatile(
                            "mma.sync.aligned.m16n8k8.row.col.f32.tf32.tf32.f32 "
                            "{%0,%1,%2,%3},{%4,%5,%6,%7},{%8,%9},{%0,%1,%2,%3};"
                            : "+f"(acc[mi][ni][0]), "+f"(acc[mi][ni][1]),
                              "+f"(acc[mi][ni][2]), "+f"(acc[mi][ni][3])
                            : "r"(a[cur][mi][0]), "r"(a[cur][mi][1]),
                              "r"(a[cur][mi][2]), "r"(a[cur][mi][3]),
                              "r"(b[cur][ni][0]), "r"(b[cur][ni][1]));
            }
        }

        // ---- register epilogue: gate + pair-combine (shfl_xor 4) + compose ----
        const float t = (float)(strip * TSTRIP + iter * 2 + tp) * (1.0f / 2048.0f);
        float rt[8];
        #pragma unroll
        for (int ni = 0; ni < 8; ni++)
            rt[ni] = 1.0f + tanha(0.5f * (t * rv[ni] + rbv[ni]));   // 2*sigmoid(v)

        #pragma unroll
        for (int mi = 0; mi < 2; mi++)
            #pragma unroll
            for (int ni = 0; ni < 8; ni++)
                #pragma unroll
                for (int hl = 0; hl < 2; hl++) {
                    float zg = acc[mi][ni][hl * 2 + 0];
                    float zh = acc[mi][ni][hl * 2 + 1];
                    float G = rt[ni] * (0.5f + 0.5f * tanha(0.5f * (zg + gbv[ni])));
                    float H = rt[ni] * tanha(zh + hbv[ni]);
                    float Gp = __shfl_xor_sync(0xffffffffu, G, 4);
                    float Hp = __shfl_xor_sync(0xffffffffu, H, 4);
                    // on tp==0 lanes: own=(G0,H0), partner=(G1,H1)
                    float A2 = Gp * G;
                    float B2 = Gp * H + Hp;
                    sB[mi][hl][ni] = A2 * sB[mi][hl][ni] + B2;
                    sA[mi][hl][ni] *= A2;
                }
    }

    // drain remaining async groups (stages 254,255 tails) before exit writes
    asm volatile("cp.async.wait_group 0;" ::: "memory");

    // ---- write strip transform (tp==0 lanes own valid state) ----
    if (tp == 0) {
        #pragma unroll
        for (int mi = 0; mi < 2; mi++)
            #pragma unroll
            for (int hl = 0; hl < 2; hl++)
                #pragma unroll
                for (int ni = 0; ni < 8; ni++) {
                    int bb = (wm >> 1) + mi * 8 + hl * 4 + (grp >> 1);
                    int o  = o_base + (wn >> 1) + ni * 4 + tig;
                    size_t gi = (size_t)(strip * Bdim + bb) * Odim + o;
                    g_As[gi] = sA[mi][hl][ni];
                    g_Bs[gi] = sB[mi][hl][ni];
                }
    }
}

// ---------------- strip combine ----------------
__global__ void rnn_combine(float* __restrict__ out)
{
    int idx = blockIdx.x * 256 + threadIdx.x;   // = b*512 + o
    float y = 0.0f;
    #pragma unroll 8
    for (int s = 0; s < NSTRIPS; s++)
        y = g_As[s * (Bdim * Odim) + idx] * y + g_Bs[s * (Bdim * Odim) + idx];
    out[idx] = y;
}

extern "C" void kernel_launch(void* const* d_in, const int* in_sizes, int n_in,
                              void* d_out, int out_size)
{
    const float* x  = (const float*)d_in[0];
    const float* g  = (const float*)d_in[1];
    const float* gb = (const float*)d_in[2];
    const float* h  = (const float*)d_in[3];
    const float* hb = (const float*)d_in[4];
    const float* r  = (const float*)d_in[5];
    const float* rb = (const float*)d_in[6];

    cudaFuncSetAttribute((const void*)rnn_gemm_scan,
                         cudaFuncAttributeMaxDynamicSharedMemorySize, SM_TOTAL);

    prep_w<<<dim3(16, 16, 2), dim3(32, 8)>>>(g, h);
    rnn_gemm_scan<<<dim3(8, NSTRIPS), 256, SM_TOTAL>>>(x, gb, hb, r, rb);
    rnn_combine<<<(Bdim * Odim) / 256, 256>>>((float*)d_out);
}